// round 3
// baseline (speedup 1.0000x reference)
#include <cuda_runtime.h>
#include <cstddef>

// Problem constants
#define B_  2
#define H_  16
#define S_  4096
#define DH  64
#define E_  1024        // H_*DH
#define SEG 1024

// ---------------------------------------------------------------------------
// Scratch (device globals — no runtime allocation allowed)
// ---------------------------------------------------------------------------
__device__ float g_q[(size_t)B_ * H_ * S_ * DH];      // [b][h][s][d]
__device__ float g_k[(size_t)B_ * H_ * S_ * DH];
__device__ float g_v[(size_t)B_ * H_ * S_ * DH];
__device__ float g_attn[(size_t)B_ * S_ * E_];        // [b][s][h*64+d]

// ---------------------------------------------------------------------------
// GEMM: C[m][n] = sum_k A[m][k] * W[n][k] + bias[n]     (both row-major, "NT")
// mode 0: scatter into g_q/g_k/g_v  (QKV projection, N=3072)
// mode 1: plain row-major store into C (output projection)
// Tiles: BM=BN=128, BK=16, 256 threads, 8x8 per-thread micro-tile.
// ---------------------------------------------------------------------------
__global__ __launch_bounds__(256) void gemm_nt_kernel(
    const float* __restrict__ A, const float* __restrict__ W,
    const float* __restrict__ bias, float* __restrict__ C,
    int M, int N, int K, int mode)
{
    __shared__ float As[16][132];   // [k][m], padded
    __shared__ float Bs[16][132];   // [k][n], padded

    const float* Ap = A ? A : g_attn;

    const int tid = threadIdx.x;
    const int tx = tid & 15;
    const int ty = tid >> 4;
    const int m0 = blockIdx.y << 7;
    const int n0 = blockIdx.x << 7;

    float acc[8][8];
#pragma unroll
    for (int i = 0; i < 8; i++)
#pragma unroll
        for (int j = 0; j < 8; j++) acc[i][j] = 0.f;

    const int lrow = tid >> 2;          // 0..63
    const int lc4  = (tid & 3) << 2;    // 0,4,8,12

    for (int k0 = 0; k0 < K; k0 += 16) {
#pragma unroll
        for (int f = 0; f < 2; f++) {
            int row = lrow + f * 64;
            float4 v = *(const float4*)(Ap + (size_t)(m0 + row) * K + k0 + lc4);
            As[lc4 + 0][row] = v.x;
            As[lc4 + 1][row] = v.y;
            As[lc4 + 2][row] = v.z;
            As[lc4 + 3][row] = v.w;
            float4 w = *(const float4*)(W + (size_t)(n0 + row) * K + k0 + lc4);
            Bs[lc4 + 0][row] = w.x;
            Bs[lc4 + 1][row] = w.y;
            Bs[lc4 + 2][row] = w.z;
            Bs[lc4 + 3][row] = w.w;
        }
        __syncthreads();

#pragma unroll
        for (int k = 0; k < 16; k++) {
            float4 a0 = *(const float4*)&As[k][ty * 8];
            float4 a1 = *(const float4*)&As[k][ty * 8 + 4];
            float4 b0 = *(const float4*)&Bs[k][tx * 8];
            float4 b1 = *(const float4*)&Bs[k][tx * 8 + 4];
            float a[8] = {a0.x, a0.y, a0.z, a0.w, a1.x, a1.y, a1.z, a1.w};
            float b[8] = {b0.x, b0.y, b0.z, b0.w, b1.x, b1.y, b1.z, b1.w};
#pragma unroll
            for (int i = 0; i < 8; i++)
#pragma unroll
                for (int j = 0; j < 8; j++)
                    acc[i][j] = fmaf(a[i], b[j], acc[i][j]);
        }
        __syncthreads();
    }

    // Epilogue
#pragma unroll
    for (int i = 0; i < 8; i++) {
        int m = m0 + ty * 8 + i;
#pragma unroll
        for (int j = 0; j < 8; j++) {
            int n = n0 + tx * 8 + j;
            float v = acc[i][j] + bias[n];
            if (mode == 0) {
                // n = t*1024 + h*64 + d ; m = b*4096 + s
                int t  = n >> 10;
                int h  = (n >> 6) & 15;
                int d  = n & 63;
                int bb = m >> 12;
                int s  = m & 4095;
                float* dst = (t == 0) ? g_q : (t == 1) ? g_k : g_v;
                dst[(((size_t)bb * H_ + h) * S_ + s) * DH + d] = v;
            } else {
                C[(size_t)m * N + n] = v;
            }
        }
    }
}

// ---------------------------------------------------------------------------
// Block-diagonal flash attention.
// One block = (b, h, 64-query tile). Keys restricted to the query's segment
// (SEG=1024), processed as 16 key-tiles of 64. 256 threads, 4x4 micro-tile.
// Q,K stored transposed [d][row] in smem -> conflict-free LDS.128 outer
// products for S = Q K^T. P staged transposed [key][row] so PV is the same
// outer-product shape against V [key][d].
// ---------------------------------------------------------------------------
#define STR 68
#define ATT_SMEM (4 * 64 * STR * (int)sizeof(float))  // Qt,Kt,Vs,Pt = 69632 B

__global__ __launch_bounds__(256) void attn_kernel()
{
    extern __shared__ float sm[];
    float* Qt = sm;                  // [d][row]   64 x STR
    float* Kt = sm + 64 * STR;       // [d][key]
    float* Vs = sm + 2 * 64 * STR;   // [key][d]
    float* Pt = sm + 3 * 64 * STR;   // [key][row]

    const int tid = threadIdx.x;
    const int tx = tid & 15;
    const int ty = tid >> 4;
    const int qt = blockIdx.x;       // 0..63 (64 query tiles per (b,h))
    const int h  = blockIdx.y;
    const int b  = blockIdx.z;
    const int s0 = qt << 6;
    const int kbase = s0 & ~(SEG - 1);

    const size_t headoff = (((size_t)b * H_ + h) * S_) * DH;
    const float* qp = g_q + headoff + (size_t)s0 * DH;

    const int lrow = tid >> 4;         // 0..15
    const int lc4  = (tid & 15) << 2;  // 0..60 step 4

    // Load Q tile transposed, pre-scaled by 1/sqrt(Dh)=0.125
#pragma unroll
    for (int f = 0; f < 4; f++) {
        int row = lrow + f * 16;
        float4 v = *(const float4*)(qp + row * DH + lc4);
        Qt[(lc4 + 0) * STR + row] = v.x * 0.125f;
        Qt[(lc4 + 1) * STR + row] = v.y * 0.125f;
        Qt[(lc4 + 2) * STR + row] = v.z * 0.125f;
        Qt[(lc4 + 3) * STR + row] = v.w * 0.125f;
    }

    float m_i[4], l_i[4], o[4][4];
#pragma unroll
    for (int i = 0; i < 4; i++) {
        m_i[i] = -1e30f;
        l_i[i] = 0.f;
#pragma unroll
        for (int j = 0; j < 4; j++) o[i][j] = 0.f;
    }

    for (int kt = 0; kt < 16; kt++) {
        __syncthreads();  // protect Kt/Vs/Pt against previous iteration's readers
        const float* kp = g_k + headoff + (size_t)(kbase + kt * 64) * DH;
        const float* vp = g_v + headoff + (size_t)(kbase + kt * 64) * DH;
#pragma unroll
        for (int f = 0; f < 4; f++) {
            int row = lrow + f * 16;
            float4 v = *(const float4*)(kp + row * DH + lc4);
            Kt[(lc4 + 0) * STR + row] = v.x;
            Kt[(lc4 + 1) * STR + row] = v.y;
            Kt[(lc4 + 2) * STR + row] = v.z;
            Kt[(lc4 + 3) * STR + row] = v.w;
            float4 w = *(const float4*)(vp + row * DH + lc4);
            *(float4*)&Vs[row * STR + lc4] = w;
        }
        __syncthreads();

        // S tile: sacc[i][j] = (q_{ty*4+i} . k_{tx*4+j}) * scale
        float sacc[4][4];
#pragma unroll
        for (int i = 0; i < 4; i++)
#pragma unroll
            for (int j = 0; j < 4; j++) sacc[i][j] = 0.f;

#pragma unroll 16
        for (int d = 0; d < 64; d++) {
            float4 qa = *(const float4*)&Qt[d * STR + ty * 4];
            float4 kb = *(const float4*)&Kt[d * STR + tx * 4];
            float qv[4] = {qa.x, qa.y, qa.z, qa.w};
            float kv[4] = {kb.x, kb.y, kb.z, kb.w};
#pragma unroll
            for (int i = 0; i < 4; i++)
#pragma unroll
                for (int j = 0; j < 4; j++)
                    sacc[i][j] = fmaf(qv[i], kv[j], sacc[i][j]);
        }

        // Online softmax per query row; reduce across the 16 tx lanes
#pragma unroll
        for (int i = 0; i < 4; i++) {
            float mx = fmaxf(fmaxf(sacc[i][0], sacc[i][1]),
                             fmaxf(sacc[i][2], sacc[i][3]));
#pragma unroll
            for (int off = 8; off; off >>= 1)
                mx = fmaxf(mx, __shfl_xor_sync(0xffffffffu, mx, off));
            float nm = fmaxf(m_i[i], mx);
            float corr = __expf(m_i[i] - nm);
            float rs = 0.f;
#pragma unroll
            for (int j = 0; j < 4; j++) {
                float p = __expf(sacc[i][j] - nm);
                sacc[i][j] = p;
                rs += p;
            }
#pragma unroll
            for (int off = 8; off; off >>= 1)
                rs += __shfl_xor_sync(0xffffffffu, rs, off);
            l_i[i] = l_i[i] * corr + rs;
            m_i[i] = nm;
#pragma unroll
            for (int j = 0; j < 4; j++) o[i][j] *= corr;
            // stage P transposed: Pt[key][row]
#pragma unroll
            for (int j = 0; j < 4; j++)
                Pt[(tx * 4 + j) * STR + ty * 4 + i] = sacc[i][j];
        }
        __syncthreads();

        // O += P^T-outer-product V : o[i][j] += P[q=ty*4+i][key] * V[key][d=tx*4+j]
#pragma unroll 8
        for (int key = 0; key < 64; key++) {
            float4 pa = *(const float4*)&Pt[key * STR + ty * 4];
            float4 vb = *(const float4*)&Vs[key * STR + tx * 4];
            float pv[4] = {pa.x, pa.y, pa.z, pa.w};
            float vv[4] = {vb.x, vb.y, vb.z, vb.w};
#pragma unroll
            for (int i = 0; i < 4; i++)
#pragma unroll
                for (int j = 0; j < 4; j++)
                    o[i][j] = fmaf(pv[i], vv[j], o[i][j]);
        }
    }

    // Normalize and write to g_attn[b][s][h*64+d]
#pragma unroll
    for (int i = 0; i < 4; i++) {
        float inv = 1.f / l_i[i];
        float4 r = make_float4(o[i][0] * inv, o[i][1] * inv,
                               o[i][2] * inv, o[i][3] * inv);
        *(float4*)&g_attn[((size_t)b * S_ + s0 + ty * 4 + i) * E_ + h * DH + tx * 4] = r;
    }
}

// ---------------------------------------------------------------------------
// kernel_launch: qkv GEMM -> attention -> out GEMM
// Inputs (metadata order): x, w_qkv, b_qkv, w_out, b_out. Output fp32 [B,S,E].
// ---------------------------------------------------------------------------
extern "C" void kernel_launch(void* const* d_in, const int* in_sizes, int n_in,
                              void* d_out, int out_size)
{
    (void)in_sizes; (void)n_in; (void)out_size;
    const float* x     = (const float*)d_in[0];
    const float* w_qkv = (const float*)d_in[1];
    const float* b_qkv = (const float*)d_in[2];
    const float* w_out = (const float*)d_in[3];
    const float* b_out = (const float*)d_in[4];
    float* out = (float*)d_out;

    cudaFuncSetAttribute(attn_kernel,
                         cudaFuncAttributeMaxDynamicSharedMemorySize, ATT_SMEM);

    // 1) QKV projection: [8192,1024] x [3072,1024]^T -> scatter q/k/v
    {
        dim3 grid(3 * E_ / 128, (B_ * S_) / 128);   // (24, 64)
        gemm_nt_kernel<<<grid, 256>>>(x, w_qkv, b_qkv, nullptr,
                                      B_ * S_, 3 * E_, E_, 0);
    }
    // 2) Segmented attention
    {
        dim3 grid(S_ / 64, H_, B_);                 // (64, 16, 2)
        attn_kernel<<<grid, 256, ATT_SMEM>>>();
    }
    // 3) Output projection: [8192,1024] x [1024,1024]^T -> d_out
    {
        dim3 grid(E_ / 128, (B_ * S_) / 128);       // (8, 64)
        gemm_nt_kernel<<<grid, 256>>>(nullptr, w_out, b_out, out,
                                      B_ * S_, E_, E_, 1);
    }
}

// round 4
// speedup vs baseline: 1.1823x; 1.1823x over previous
#include <cuda_runtime.h>
#include <cstddef>

// Problem constants
#define B_  2
#define H_  16
#define S_  4096
#define DH  64
#define E_  1024        // H_*DH
#define SEG 1024

// ---------------------------------------------------------------------------
// Scratch (device globals — no runtime allocation allowed)
// ---------------------------------------------------------------------------
__device__ float g_q[(size_t)B_ * H_ * S_ * DH];      // [b][h][s][d]
__device__ float g_k[(size_t)B_ * H_ * S_ * DH];
__device__ float g_v[(size_t)B_ * H_ * S_ * DH];
__device__ float g_attn[(size_t)B_ * S_ * E_];        // [b][s][h*64+d]

// ---------------------------------------------------------------------------
// GEMM: C[m][n] = sum_k A[m][k] * W[n][k] + bias[n]   (row-major "NT")
// mode 0: scatter into g_q/g_k/g_v  (QKV projection, N=3072)
// mode 1: plain row-major store into C (output projection)
// 128x128x16 tile, 256 threads, 8x8 micro-tile in 4+4 split layout
// (thread cols {tx*4, 64+tx*4}) for conflict-free LDS.128.
// Double-buffered smem + register prefetch; 2 CTAs/SM via launch_bounds.
// ---------------------------------------------------------------------------
__global__ __launch_bounds__(256, 2) void gemm_nt_kernel(
    const float* __restrict__ A, const float* __restrict__ W,
    const float* __restrict__ bias, float* __restrict__ C,
    int M, int N, int K, int mode)
{
    __shared__ float As[2][16][132];   // [buf][k][m], padded
    __shared__ float Bs[2][16][132];   // [buf][k][n], padded

    const float* Ap = A ? A : g_attn;

    const int tid = threadIdx.x;
    const int tx = tid & 15;
    const int ty = tid >> 4;
    const int m0 = blockIdx.y << 7;
    const int n0 = blockIdx.x << 7;

    float acc[8][8];
#pragma unroll
    for (int i = 0; i < 8; i++)
#pragma unroll
        for (int j = 0; j < 8; j++) acc[i][j] = 0.f;

    const int lrow = tid >> 2;          // 0..63
    const int lc4  = (tid & 3) << 2;    // 0,4,8,12

    float4 ra[2], rb[2];

    // --- initial tile (k0 = 0) straight into buffer 0 ---
#pragma unroll
    for (int f = 0; f < 2; f++) {
        int row = lrow + f * 64;
        ra[f] = *(const float4*)(Ap + (size_t)(m0 + row) * K + lc4);
        rb[f] = *(const float4*)(W  + (size_t)(n0 + row) * K + lc4);
    }
#pragma unroll
    for (int f = 0; f < 2; f++) {
        int row = lrow + f * 64;
        As[0][lc4 + 0][row] = ra[f].x; As[0][lc4 + 1][row] = ra[f].y;
        As[0][lc4 + 2][row] = ra[f].z; As[0][lc4 + 3][row] = ra[f].w;
        Bs[0][lc4 + 0][row] = rb[f].x; Bs[0][lc4 + 1][row] = rb[f].y;
        Bs[0][lc4 + 2][row] = rb[f].z; Bs[0][lc4 + 3][row] = rb[f].w;
    }
    __syncthreads();

    int p = 0;
    for (int k0 = 16; k0 <= K; k0 += 16) {
        // Prefetch next tile into registers (overlaps with compute below)
        if (k0 < K) {
#pragma unroll
            for (int f = 0; f < 2; f++) {
                int row = lrow + f * 64;
                ra[f] = *(const float4*)(Ap + (size_t)(m0 + row) * K + k0 + lc4);
                rb[f] = *(const float4*)(W  + (size_t)(n0 + row) * K + k0 + lc4);
            }
        }

        // Compute on buffer p
#pragma unroll
        for (int k = 0; k < 16; k++) {
            float4 a0 = *(const float4*)&As[p][k][ty * 4];
            float4 a1 = *(const float4*)&As[p][k][64 + ty * 4];
            float4 b0 = *(const float4*)&Bs[p][k][tx * 4];
            float4 b1 = *(const float4*)&Bs[p][k][64 + tx * 4];
            float a[8] = {a0.x, a0.y, a0.z, a0.w, a1.x, a1.y, a1.z, a1.w};
            float b[8] = {b0.x, b0.y, b0.z, b0.w, b1.x, b1.y, b1.z, b1.w};
#pragma unroll
            for (int i = 0; i < 8; i++)
#pragma unroll
                for (int j = 0; j < 8; j++)
                    acc[i][j] = fmaf(a[i], b[j], acc[i][j]);
        }

        // Store prefetched regs into the other buffer
        if (k0 < K) {
            p ^= 1;
#pragma unroll
            for (int f = 0; f < 2; f++) {
                int row = lrow + f * 64;
                As[p][lc4 + 0][row] = ra[f].x; As[p][lc4 + 1][row] = ra[f].y;
                As[p][lc4 + 2][row] = ra[f].z; As[p][lc4 + 3][row] = ra[f].w;
                Bs[p][lc4 + 0][row] = rb[f].x; Bs[p][lc4 + 1][row] = rb[f].y;
                Bs[p][lc4 + 2][row] = rb[f].z; Bs[p][lc4 + 3][row] = rb[f].w;
            }
            __syncthreads();
        }
    }

    // Epilogue — rows {ty*4+i, 64+ty*4+i}, cols {tx*4+j, 64+tx*4+j}
#pragma unroll
    for (int i = 0; i < 8; i++) {
        int m = m0 + ty * 4 + (i & 3) + ((i >> 2) << 6);
#pragma unroll
        for (int jh = 0; jh < 2; jh++) {
            int n = n0 + tx * 4 + (jh << 6);
            float4 bv = *(const float4*)(bias + n);
            float4 r;
            r.x = acc[i][jh * 4 + 0] + bv.x;
            r.y = acc[i][jh * 4 + 1] + bv.y;
            r.z = acc[i][jh * 4 + 2] + bv.z;
            r.w = acc[i][jh * 4 + 3] + bv.w;
            if (mode == 0) {
                // n = t*1024 + h*64 + d ; m = b*4096 + s ; d=tx*4 (consec 4)
                int t  = n >> 10;
                int h  = (n >> 6) & 15;
                int d  = n & 63;
                int bb = m >> 12;
                int s  = m & 4095;
                float* dst = (t == 0) ? g_q : (t == 1) ? g_k : g_v;
                *(float4*)&dst[(((size_t)bb * H_ + h) * S_ + s) * DH + d] = r;
            } else {
                *(float4*)&C[(size_t)m * N + n] = r;
            }
        }
    }
}

// ---------------------------------------------------------------------------
// Block-diagonal flash attention.
// One block = (b, h, 64-query tile); 16 key-tiles of 64 within the segment.
// 256 threads, 4x4 micro-tile. Q/K transposed [d][row] in smem; P staged
// transposed so PV is the same outer-product shape. K/V tiles prefetched
// into registers one iteration ahead to hide global latency.
// ---------------------------------------------------------------------------
#define STR 68
#define ATT_SMEM (4 * 64 * STR * (int)sizeof(float))  // Qt,Kt,Vs,Pt = 69632 B

__global__ __launch_bounds__(256) void attn_kernel()
{
    extern __shared__ float sm[];
    float* Qt = sm;                  // [d][row]   64 x STR
    float* Kt = sm + 64 * STR;       // [d][key]
    float* Vs = sm + 2 * 64 * STR;   // [key][d]
    float* Pt = sm + 3 * 64 * STR;   // [key][row]

    const int tid = threadIdx.x;
    const int tx = tid & 15;
    const int ty = tid >> 4;
    const int qt = blockIdx.x;       // 0..63
    const int h  = blockIdx.y;
    const int b  = blockIdx.z;
    const int s0 = qt << 6;
    const int kbase = s0 & ~(SEG - 1);

    const size_t headoff = (((size_t)b * H_ + h) * S_) * DH;
    const float* qp = g_q + headoff + (size_t)s0 * DH;

    const int lrow = tid >> 4;         // 0..15
    const int lc4  = (tid & 15) << 2;  // 0..60 step 4

    // Load Q tile transposed, pre-scaled by 1/sqrt(Dh)=0.125
#pragma unroll
    for (int f = 0; f < 4; f++) {
        int row = lrow + f * 16;
        float4 v = *(const float4*)(qp + row * DH + lc4);
        Qt[(lc4 + 0) * STR + row] = v.x * 0.125f;
        Qt[(lc4 + 1) * STR + row] = v.y * 0.125f;
        Qt[(lc4 + 2) * STR + row] = v.z * 0.125f;
        Qt[(lc4 + 3) * STR + row] = v.w * 0.125f;
    }

    float m_i[4], l_i[4], o[4][4];
#pragma unroll
    for (int i = 0; i < 4; i++) {
        m_i[i] = -1e30f;
        l_i[i] = 0.f;
#pragma unroll
        for (int j = 0; j < 4; j++) o[i][j] = 0.f;
    }

    // Prefetch K/V tile 0 into registers
    float4 rk[4], rv[4];
    {
        const float* kp = g_k + headoff + (size_t)kbase * DH;
        const float* vp = g_v + headoff + (size_t)kbase * DH;
#pragma unroll
        for (int f = 0; f < 4; f++) {
            int row = lrow + f * 16;
            rk[f] = *(const float4*)(kp + row * DH + lc4);
            rv[f] = *(const float4*)(vp + row * DH + lc4);
        }
    }

    for (int kt = 0; kt < 16; kt++) {
        __syncthreads();  // previous iteration's Kt/Vs/Pt readers done
#pragma unroll
        for (int f = 0; f < 4; f++) {
            int row = lrow + f * 16;
            Kt[(lc4 + 0) * STR + row] = rk[f].x;
            Kt[(lc4 + 1) * STR + row] = rk[f].y;
            Kt[(lc4 + 2) * STR + row] = rk[f].z;
            Kt[(lc4 + 3) * STR + row] = rk[f].w;
            *(float4*)&Vs[row * STR + lc4] = rv[f];
        }
        __syncthreads();

        // Prefetch next K/V tile (overlaps S-compute below)
        if (kt < 15) {
            const float* kp = g_k + headoff + (size_t)(kbase + (kt + 1) * 64) * DH;
            const float* vp = g_v + headoff + (size_t)(kbase + (kt + 1) * 64) * DH;
#pragma unroll
            for (int f = 0; f < 4; f++) {
                int row = lrow + f * 16;
                rk[f] = *(const float4*)(kp + row * DH + lc4);
                rv[f] = *(const float4*)(vp + row * DH + lc4);
            }
        }

        // S tile: sacc[i][j] = q_{ty*4+i} . k_{tx*4+j}  (pre-scaled)
        float sacc[4][4];
#pragma unroll
        for (int i = 0; i < 4; i++)
#pragma unroll
            for (int j = 0; j < 4; j++) sacc[i][j] = 0.f;

#pragma unroll 16
        for (int d = 0; d < 64; d++) {
            float4 qa = *(const float4*)&Qt[d * STR + ty * 4];
            float4 kb = *(const float4*)&Kt[d * STR + tx * 4];
            float qv[4] = {qa.x, qa.y, qa.z, qa.w};
            float kv[4] = {kb.x, kb.y, kb.z, kb.w};
#pragma unroll
            for (int i = 0; i < 4; i++)
#pragma unroll
                for (int j = 0; j < 4; j++)
                    sacc[i][j] = fmaf(qv[i], kv[j], sacc[i][j]);
        }

        // Online softmax per query row; reduce across the 16 tx lanes
#pragma unroll
        for (int i = 0; i < 4; i++) {
            float mx = fmaxf(fmaxf(sacc[i][0], sacc[i][1]),
                             fmaxf(sacc[i][2], sacc[i][3]));
#pragma unroll
            for (int off = 8; off; off >>= 1)
                mx = fmaxf(mx, __shfl_xor_sync(0xffffffffu, mx, off));
            float nm = fmaxf(m_i[i], mx);
            float corr = __expf(m_i[i] - nm);
            float rs = 0.f;
#pragma unroll
            for (int j = 0; j < 4; j++) {
                float p = __expf(sacc[i][j] - nm);
                sacc[i][j] = p;
                rs += p;
            }
#pragma unroll
            for (int off = 8; off; off >>= 1)
                rs += __shfl_xor_sync(0xffffffffu, rs, off);
            l_i[i] = l_i[i] * corr + rs;
            m_i[i] = nm;
#pragma unroll
            for (int j = 0; j < 4; j++) o[i][j] *= corr;
            // stage P transposed: Pt[key][row]
#pragma unroll
            for (int j = 0; j < 4; j++)
                Pt[(tx * 4 + j) * STR + ty * 4 + i] = sacc[i][j];
        }
        __syncthreads();

        // O += P^T outer-product V
#pragma unroll 8
        for (int key = 0; key < 64; key++) {
            float4 pa = *(const float4*)&Pt[key * STR + ty * 4];
            float4 vb = *(const float4*)&Vs[key * STR + tx * 4];
            float pv[4] = {pa.x, pa.y, pa.z, pa.w};
            float vv[4] = {vb.x, vb.y, vb.z, vb.w};
#pragma unroll
            for (int i = 0; i < 4; i++)
#pragma unroll
                for (int j = 0; j < 4; j++)
                    o[i][j] = fmaf(pv[i], vv[j], o[i][j]);
        }
    }

    // Normalize and write to g_attn[b][s][h*64+d]
#pragma unroll
    for (int i = 0; i < 4; i++) {
        float inv = 1.f / l_i[i];
        float4 r = make_float4(o[i][0] * inv, o[i][1] * inv,
                               o[i][2] * inv, o[i][3] * inv);
        *(float4*)&g_attn[((size_t)b * S_ + s0 + ty * 4 + i) * E_ + h * DH + tx * 4] = r;
    }
}

// ---------------------------------------------------------------------------
// kernel_launch: qkv GEMM -> attention -> out GEMM
// Inputs (metadata order): x, w_qkv, b_qkv, w_out, b_out. Output fp32 [B,S,E].
// ---------------------------------------------------------------------------
extern "C" void kernel_launch(void* const* d_in, const int* in_sizes, int n_in,
                              void* d_out, int out_size)
{
    (void)in_sizes; (void)n_in; (void)out_size;
    const float* x     = (const float*)d_in[0];
    const float* w_qkv = (const float*)d_in[1];
    const float* b_qkv = (const float*)d_in[2];
    const float* w_out = (const float*)d_in[3];
    const float* b_out = (const float*)d_in[4];
    float* out = (float*)d_out;

    cudaFuncSetAttribute(attn_kernel,
                         cudaFuncAttributeMaxDynamicSharedMemorySize, ATT_SMEM);

    // 1) QKV projection: [8192,1024] x [3072,1024]^T -> scatter q/k/v
    {
        dim3 grid(3 * E_ / 128, (B_ * S_) / 128);   // (24, 64)
        gemm_nt_kernel<<<grid, 256>>>(x, w_qkv, b_qkv, nullptr,
                                      B_ * S_, 3 * E_, E_, 0);
    }
    // 2) Segmented attention
    {
        dim3 grid(S_ / 64, H_, B_);                 // (64, 16, 2)
        attn_kernel<<<grid, 256, ATT_SMEM>>>();
    }
    // 3) Output projection: [8192,1024] x [1024,1024]^T -> d_out
    {
        dim3 grid(E_ / 128, (B_ * S_) / 128);       // (8, 64)
        gemm_nt_kernel<<<grid, 256>>>(nullptr, w_out, b_out, out,
                                      B_ * S_, E_, E_, 1);
    }
}

// round 10
// speedup vs baseline: 1.3635x; 1.1533x over previous
#include <cuda_runtime.h>
#include <cstdint>
#include <cstddef>

// Problem constants
#define B_  2
#define H_  16
#define S_  4096
#define DH  64
#define E_  1024
#define SEG 1024
#define GK  1024          // K of both GEMMs

// ---------------------------------------------------------------------------
// Scratch (device globals — no runtime allocation allowed)
// ---------------------------------------------------------------------------
__device__ float g_q[(size_t)B_ * H_ * S_ * DH];      // [b][h][s][d]
__device__ float g_k[(size_t)B_ * H_ * S_ * DH];
__device__ float g_v[(size_t)B_ * H_ * S_ * DH];
__device__ float g_attn[(size_t)B_ * S_ * E_];        // [b][s][h*64+d]

// ---------------------------------------------------------------------------
// tf32 helpers (sm_80-era PTX only — NO tcgen05 / cta_group: harness compiles
// PTX at target sm_103 without the 'a' suffix)
// ---------------------------------------------------------------------------
__device__ __forceinline__ void tf32_split(float v, uint32_t& h, uint32_t& l) {
    asm("cvt.rna.tf32.f32 %0, %1;" : "=r"(h) : "f"(v));
    float r = v - __uint_as_float(h);
    asm("cvt.rna.tf32.f32 %0, %1;" : "=r"(l) : "f"(r));
}

__device__ __forceinline__ void mma_tf32(float* c,
    uint32_t a0, uint32_t a1, uint32_t a2, uint32_t a3,
    uint32_t b0, uint32_t b1)
{
    asm volatile(
        "mma.sync.aligned.m16n8k8.row.col.f32.tf32.tf32.f32 "
        "{%0,%1,%2,%3}, {%4,%5,%6,%7}, {%8,%9}, {%0,%1,%2,%3};"
        : "+f"(c[0]), "+f"(c[1]), "+f"(c[2]), "+f"(c[3])
        : "r"(a0), "r"(a1), "r"(a2), "r"(a3), "r"(b0), "r"(b1));
}

// ---------------------------------------------------------------------------
// 3xTF32 GEMM: C[m][n] = sum_k A[m][k]*W[n][k] + bias[n]   ("NT", K=1024)
// BM=BN=128, BK=16. 8 warps as 2(row)x4(col); warp tile 64x32; atoms m16n8k8.
// SMEM holds hi/lo tf32 fragments in *fragment order*:
//   A: idx = ks*1057 + am*132 + reg*33 + lane    (reg = (r%16>=8) + 2*(k%8>=4))
//   B: idx = ks*1089 + an*68  + reg*34 + lane    (reg = (k%8>=4))
// Stride residues mod 4 = {0,2,1,3} across the 4 writer subgroups -> STS
// scatter is bank-conflict-free; frag reads are consecutive-lane LDS.32.
// Double-buffered + register prefetch. mode 0: scatter q/k/v; mode 1: store C.
// ---------------------------------------------------------------------------
#define AHI 0
#define ALO 2114
#define BHI 4228
#define BLO 6406
#define BUFU 8584                       // uint32 per buffer
#define GEMM_SMEM (2 * BUFU * 4)        // 68672 bytes

struct ChunkRegs { float4 ra[2], rb[2]; };

__device__ __forceinline__ void ldg_chunk(ChunkRegs& r, const float* Ap,
                                          const float* W, int m0, int n0,
                                          int c, int tid)
{
#pragma unroll
    for (int i = 0; i < 2; i++) {
        int f4 = tid + i * 256;
        int row = f4 >> 2;
        int c0 = (f4 & 3) << 2;
        r.ra[i] = *(const float4*)(Ap + (size_t)(m0 + row) * GK + c * 16 + c0);
        r.rb[i] = *(const float4*)(W  + (size_t)(n0 + row) * GK + c * 16 + c0);
    }
}

__device__ __forceinline__ void sts_chunk(uint32_t* buf, const ChunkRegs& r,
                                          int tid)
{
#pragma unroll
    for (int i = 0; i < 2; i++) {
        int f4 = tid + i * 256;
        int row = f4 >> 2;
        int c0 = (f4 & 3) << 2;
        // ---- A fragment scatter ----
        {
            int am = row >> 4, rr = row & 15;
            int ks = c0 >> 3;
            int reg = (rr >> 3) + (((c0 & 7) >> 2) << 1);
            int base = ks * 1057 + am * 132 + reg * 33 + (rr & 7) * 4;
            uint32_t h, l;
            tf32_split(r.ra[i].x, h, l); buf[AHI + base + 0] = h; buf[ALO + base + 0] = l;
            tf32_split(r.ra[i].y, h, l); buf[AHI + base + 1] = h; buf[ALO + base + 1] = l;
            tf32_split(r.ra[i].z, h, l); buf[AHI + base + 2] = h; buf[ALO + base + 2] = l;
            tf32_split(r.ra[i].w, h, l); buf[AHI + base + 3] = h; buf[ALO + base + 3] = l;
        }
        // ---- B fragment scatter ----
        {
            int an = row >> 3, nn = row & 7;
            int ks = c0 >> 3;
            int reg = (c0 & 7) >> 2;
            int base = ks * 1089 + an * 68 + reg * 34 + nn * 4;
            uint32_t h, l;
            tf32_split(r.rb[i].x, h, l); buf[BHI + base + 0] = h; buf[BLO + base + 0] = l;
            tf32_split(r.rb[i].y, h, l); buf[BHI + base + 1] = h; buf[BLO + base + 1] = l;
            tf32_split(r.rb[i].z, h, l); buf[BHI + base + 2] = h; buf[BLO + base + 2] = l;
            tf32_split(r.rb[i].w, h, l); buf[BHI + base + 3] = h; buf[BLO + base + 3] = l;
        }
    }
}

__global__ __launch_bounds__(256, 2) void gemm_tf32_kernel(
    const float* __restrict__ A, const float* __restrict__ W,
    const float* __restrict__ bias, float* __restrict__ C,
    int N, int mode)
{
    extern __shared__ char dynsm[];
    uint32_t* smu = (uint32_t*)dynsm;
    const float* Ap = A ? A : g_attn;

    const int tid  = threadIdx.x;
    const int lane = tid & 31;
    const int wid  = tid >> 5;
    const int wr   = wid >> 2;      // 0..1 (64 rows each)
    const int wc   = wid & 3;       // 0..3 (32 cols each)
    const int m0 = blockIdx.y << 7;
    const int n0 = blockIdx.x << 7;

    float acc[4][4][4];
#pragma unroll
    for (int u = 0; u < 4; u++)
#pragma unroll
        for (int t = 0; t < 4; t++)
#pragma unroll
            for (int j = 0; j < 4; j++) acc[u][t][j] = 0.f;

    ChunkRegs cr;
    ldg_chunk(cr, Ap, W, m0, n0, 0, tid);
    sts_chunk(smu, cr, tid);
    __syncthreads();

    int p = 0;
    for (int c = 1; c <= GK / 16; c++) {
        if (c < GK / 16) ldg_chunk(cr, Ap, W, m0, n0, c, tid);

        const uint32_t* buf = smu + p * BUFU;
#pragma unroll
        for (int ks = 0; ks < 2; ks++) {
            uint32_t bh[4][2], bl[4][2];
#pragma unroll
            for (int t = 0; t < 4; t++) {
                int b = ks * 1089 + (wc * 4 + t) * 68 + lane;
                bh[t][0] = buf[BHI + b];      bh[t][1] = buf[BHI + b + 34];
                bl[t][0] = buf[BLO + b];      bl[t][1] = buf[BLO + b + 34];
            }
#pragma unroll
            for (int u = 0; u < 4; u++) {
                int a = ks * 1057 + (wr * 4 + u) * 132 + lane;
                uint32_t ah[4], al[4];
#pragma unroll
                for (int rg = 0; rg < 4; rg++) {
                    ah[rg] = buf[AHI + a + rg * 33];
                    al[rg] = buf[ALO + a + rg * 33];
                }
#pragma unroll
                for (int t = 0; t < 4; t++) {
                    mma_tf32(acc[u][t], ah[0], ah[1], ah[2], ah[3], bh[t][0], bh[t][1]);
                    mma_tf32(acc[u][t], ah[0], ah[1], ah[2], ah[3], bl[t][0], bl[t][1]);
                    mma_tf32(acc[u][t], al[0], al[1], al[2], al[3], bh[t][0], bh[t][1]);
                }
            }
        }

        if (c < GK / 16) {
            p ^= 1;
            sts_chunk(smu + p * BUFU, cr, tid);
            __syncthreads();
        }
    }

    // Epilogue: c0=(grp,2t), c1=(grp,2t+1), c2=(grp+8,2t), c3=(grp+8,2t+1)
    const int grp = lane >> 2;
    const int tig = lane & 3;
#pragma unroll
    for (int u = 0; u < 4; u++) {
#pragma unroll
        for (int part = 0; part < 2; part++) {
            int m = m0 + wr * 64 + u * 16 + grp + part * 8;
            int bb = m >> 12;
            int s  = m & 4095;
#pragma unroll
            for (int t = 0; t < 4; t++) {
                int n = n0 + wc * 32 + t * 8 + tig * 2;
                float2 bv = *(const float2*)(bias + n);
                float2 r;
                r.x = acc[u][t][part * 2 + 0] + bv.x;
                r.y = acc[u][t][part * 2 + 1] + bv.y;
                if (mode == 0) {
                    int tt = n >> 10;
                    int h  = (n >> 6) & 15;
                    int d  = n & 63;
                    float* dst = ((tt == 0) ? g_q : (tt == 1) ? g_k : g_v)
                                 + (((size_t)bb * H_ + h) * S_ + s) * DH + d;
                    *(float2*)dst = r;
                } else {
                    *(float2*)&C[(size_t)m * N + n] = r;
                }
            }
        }
    }
}

// ---------------------------------------------------------------------------
// Block-diagonal flash attention (scalar fp32, R4-proven, 2 CTAs/SM)
// ---------------------------------------------------------------------------
#define STR 68
#define ATT_SMEM (4 * 64 * STR * (int)sizeof(float))  // 69632 B

__global__ __launch_bounds__(256, 2) void attn_kernel()
{
    extern __shared__ char dynsm[];
    float* smf = (float*)dynsm;
    float* Qt = smf;
    float* Kt = smf + 64 * STR;
    float* Vs = smf + 2 * 64 * STR;
    float* Pt = smf + 3 * 64 * STR;

    const int tid = threadIdx.x;
    const int tx = tid & 15;
    const int ty = tid >> 4;
    const int qt = blockIdx.x;
    const int h  = blockIdx.y;
    const int b  = blockIdx.z;
    const int s0 = qt << 6;
    const int kbase = s0 & ~(SEG - 1);

    const size_t headoff = (((size_t)b * H_ + h) * S_) * DH;
    const float* qp = g_q + headoff + (size_t)s0 * DH;

    const int lrow = tid >> 4;
    const int lc4  = (tid & 15) << 2;

#pragma unroll
    for (int f = 0; f < 4; f++) {
        int row = lrow + f * 16;
        float4 v = *(const float4*)(qp + row * DH + lc4);
        Qt[(lc4 + 0) * STR + row] = v.x * 0.125f;
        Qt[(lc4 + 1) * STR + row] = v.y * 0.125f;
        Qt[(lc4 + 2) * STR + row] = v.z * 0.125f;
        Qt[(lc4 + 3) * STR + row] = v.w * 0.125f;
    }

    float m_i[4], l_i[4], o[4][4];
#pragma unroll
    for (int i = 0; i < 4; i++) {
        m_i[i] = -1e30f;
        l_i[i] = 0.f;
#pragma unroll
        for (int j = 0; j < 4; j++) o[i][j] = 0.f;
    }

    float4 rk[4], rv[4];
    {
        const float* kp = g_k + headoff + (size_t)kbase * DH;
        const float* vp = g_v + headoff + (size_t)kbase * DH;
#pragma unroll
        for (int f = 0; f < 4; f++) {
            int row = lrow + f * 16;
            rk[f] = *(const float4*)(kp + row * DH + lc4);
            rv[f] = *(const float4*)(vp + row * DH + lc4);
        }
    }

    for (int kt = 0; kt < 16; kt++) {
        __syncthreads();
#pragma unroll
        for (int f = 0; f < 4; f++) {
            int row = lrow + f * 16;
            Kt[(lc4 + 0) * STR + row] = rk[f].x;
            Kt[(lc4 + 1) * STR + row] = rk[f].y;
            Kt[(lc4 + 2) * STR + row] = rk[f].z;
            Kt[(lc4 + 3) * STR + row] = rk[f].w;
            *(float4*)&Vs[row * STR + lc4] = rv[f];
        }
        __syncthreads();

        if (kt < 15) {
            const float* kp = g_k + headoff + (size_t)(kbase + (kt + 1) * 64) * DH;
            const float* vp = g_v + headoff + (size_t)(kbase + (kt + 1) * 64) * DH;
#pragma unroll
            for (int f = 0; f < 4; f++) {
                int row = lrow + f * 16;
                rk[f] = *(const float4*)(kp + row * DH + lc4);
                rv[f] = *(const float4*)(vp + row * DH + lc4);
            }
        }

        float sacc[4][4];
#pragma unroll
        for (int i = 0; i < 4; i++)
#pragma unroll
            for (int j = 0; j < 4; j++) sacc[i][j] = 0.f;

#pragma unroll 16
        for (int d = 0; d < 64; d++) {
            float4 qa = *(const float4*)&Qt[d * STR + ty * 4];
            float4 kb = *(const float4*)&Kt[d * STR + tx * 4];
            float qv[4] = {qa.x, qa.y, qa.z, qa.w};
            float kv[4] = {kb.x, kb.y, kb.z, kb.w};
#pragma unroll
            for (int i = 0; i < 4; i++)
#pragma unroll
                for (int j = 0; j < 4; j++)
                    sacc[i][j] = fmaf(qv[i], kv[j], sacc[i][j]);
        }

#pragma unroll
        for (int i = 0; i < 4; i++) {
            float mx = fmaxf(fmaxf(sacc[i][0], sacc[i][1]),
                             fmaxf(sacc[i][2], sacc[i][3]));
#pragma unroll
            for (int off = 8; off; off >>= 1)
                mx = fmaxf(mx, __shfl_xor_sync(0xffffffffu, mx, off));
            float nm = fmaxf(m_i[i], mx);
            float corr = __expf(m_i[i] - nm);
            float rs = 0.f;
#pragma unroll
            for (int j = 0; j < 4; j++) {
                float pv = __expf(sacc[i][j] - nm);
                sacc[i][j] = pv;
                rs += pv;
            }
#pragma unroll
            for (int off = 8; off; off >>= 1)
                rs += __shfl_xor_sync(0xffffffffu, rs, off);
            l_i[i] = l_i[i] * corr + rs;
            m_i[i] = nm;
#pragma unroll
            for (int j = 0; j < 4; j++) o[i][j] *= corr;
#pragma unroll
            for (int j = 0; j < 4; j++)
                Pt[(tx * 4 + j) * STR + ty * 4 + i] = sacc[i][j];
        }
        __syncthreads();

#pragma unroll 8
        for (int key = 0; key < 64; key++) {
            float4 pa = *(const float4*)&Pt[key * STR + ty * 4];
            float4 vb = *(const float4*)&Vs[key * STR + tx * 4];
            float pv[4] = {pa.x, pa.y, pa.z, pa.w};
            float vv[4] = {vb.x, vb.y, vb.z, vb.w};
#pragma unroll
            for (int i = 0; i < 4; i++)
#pragma unroll
                for (int j = 0; j < 4; j++)
                    o[i][j] = fmaf(pv[i], vv[j], o[i][j]);
        }
    }

#pragma unroll
    for (int i = 0; i < 4; i++) {
        float inv = 1.f / l_i[i];
        float4 r = make_float4(o[i][0] * inv, o[i][1] * inv,
                               o[i][2] * inv, o[i][3] * inv);
        *(float4*)&g_attn[((size_t)b * S_ + s0 + ty * 4 + i) * E_ + h * DH + tx * 4] = r;
    }
}

// ---------------------------------------------------------------------------
// kernel_launch
// ---------------------------------------------------------------------------
extern "C" void kernel_launch(void* const* d_in, const int* in_sizes, int n_in,
                              void* d_out, int out_size)
{
    (void)in_sizes; (void)n_in; (void)out_size;
    const float* x     = (const float*)d_in[0];
    const float* w_qkv = (const float*)d_in[1];
    const float* b_qkv = (const float*)d_in[2];
    const float* w_out = (const float*)d_in[3];
    const float* b_out = (const float*)d_in[4];
    float* out = (float*)d_out;

    cudaFuncSetAttribute(gemm_tf32_kernel,
                         cudaFuncAttributeMaxDynamicSharedMemorySize, GEMM_SMEM);
    cudaFuncSetAttribute(attn_kernel,
                         cudaFuncAttributeMaxDynamicSharedMemorySize, ATT_SMEM);

    // 1) QKV projection: [8192,1024] x [3072,1024]^T -> scatter q/k/v
    {
        dim3 grid(3 * E_ / 128, (B_ * S_) / 128);   // (24, 64)
        gemm_tf32_kernel<<<grid, 256, GEMM_SMEM>>>(x, w_qkv, b_qkv, nullptr,
                                                   3 * E_, 0);
    }
    // 2) Segmented attention
    {
        dim3 grid(S_ / 64, H_, B_);                 // (64, 16, 2)
        attn_kernel<<<grid, 256, ATT_SMEM>>>();
    }
    // 3) Output projection: [8192,1024] x [1024,1024]^T -> d_out
    {
        dim3 grid(E_ / 128, (B_ * S_) / 128);       // (8, 64)
        gemm_tf32_kernel<<<grid, 256, GEMM_SMEM>>>(nullptr, w_out, b_out, out,
                                                   E_, 1);
    }
}

// round 12
// speedup vs baseline: 1.7742x; 1.3011x over previous
#include <cuda_runtime.h>
#include <cstdint>
#include <cstddef>

// Problem constants
#define B_  2
#define H_  16
#define S_  4096
#define DH  64
#define E_  1024
#define SEG 1024
#define GK  1024          // K of both GEMMs

// ---------------------------------------------------------------------------
// Scratch (device globals — no runtime allocation allowed)
// ---------------------------------------------------------------------------
__device__ float g_q[(size_t)B_ * H_ * S_ * DH];      // [b][h][s][d]
__device__ float g_k[(size_t)B_ * H_ * S_ * DH];
__device__ float g_v[(size_t)B_ * H_ * S_ * DH];
__device__ float g_attn[(size_t)B_ * S_ * E_];        // [b][s][h*64+d]

// ---------------------------------------------------------------------------
// tf32 helpers (sm_80-era PTX only — NO tcgen05 / cta_group: harness compiles
// PTX at target sm_103 without the 'a' suffix)
// ---------------------------------------------------------------------------
__device__ __forceinline__ void tf32_split(float v, uint32_t& h, uint32_t& l) {
    asm("cvt.rna.tf32.f32 %0, %1;" : "=r"(h) : "f"(v));
    float r = v - __uint_as_float(h);
    asm("cvt.rna.tf32.f32 %0, %1;" : "=r"(l) : "f"(r));
}
__device__ __forceinline__ uint32_t tf32_one(float v) {
    uint32_t u;
    asm("cvt.rna.tf32.f32 %0, %1;" : "=r"(u) : "f"(v));
    return u;
}

__device__ __forceinline__ void mma_tf32(float* c,
    uint32_t a0, uint32_t a1, uint32_t a2, uint32_t a3,
    uint32_t b0, uint32_t b1)
{
    asm volatile(
        "mma.sync.aligned.m16n8k8.row.col.f32.tf32.tf32.f32 "
        "{%0,%1,%2,%3}, {%4,%5,%6,%7}, {%8,%9}, {%0,%1,%2,%3};"
        : "+f"(c[0]), "+f"(c[1]), "+f"(c[2]), "+f"(c[3])
        : "r"(a0), "r"(a1), "r"(a2), "r"(a3), "r"(b0), "r"(b1));
}

// ---------------------------------------------------------------------------
// 3xTF32 GEMM (unchanged from validated R10 version)
// ---------------------------------------------------------------------------
#define AHI 0
#define ALO 2114
#define BHI 4228
#define BLO 6406
#define BUFU 8584                       // uint32 per buffer
#define GEMM_SMEM (2 * BUFU * 4)        // 68672 bytes

struct ChunkRegs { float4 ra[2], rb[2]; };

__device__ __forceinline__ void ldg_chunk(ChunkRegs& r, const float* Ap,
                                          const float* W, int m0, int n0,
                                          int c, int tid)
{
#pragma unroll
    for (int i = 0; i < 2; i++) {
        int f4 = tid + i * 256;
        int row = f4 >> 2;
        int c0 = (f4 & 3) << 2;
        r.ra[i] = *(const float4*)(Ap + (size_t)(m0 + row) * GK + c * 16 + c0);
        r.rb[i] = *(const float4*)(W  + (size_t)(n0 + row) * GK + c * 16 + c0);
    }
}

__device__ __forceinline__ void sts_chunk(uint32_t* buf, const ChunkRegs& r,
                                          int tid)
{
#pragma unroll
    for (int i = 0; i < 2; i++) {
        int f4 = tid + i * 256;
        int row = f4 >> 2;
        int c0 = (f4 & 3) << 2;
        {
            int am = row >> 4, rr = row & 15;
            int ks = c0 >> 3;
            int reg = (rr >> 3) + (((c0 & 7) >> 2) << 1);
            int base = ks * 1057 + am * 132 + reg * 33 + (rr & 7) * 4;
            uint32_t h, l;
            tf32_split(r.ra[i].x, h, l); buf[AHI + base + 0] = h; buf[ALO + base + 0] = l;
            tf32_split(r.ra[i].y, h, l); buf[AHI + base + 1] = h; buf[ALO + base + 1] = l;
            tf32_split(r.ra[i].z, h, l); buf[AHI + base + 2] = h; buf[ALO + base + 2] = l;
            tf32_split(r.ra[i].w, h, l); buf[AHI + base + 3] = h; buf[ALO + base + 3] = l;
        }
        {
            int an = row >> 3, nn = row & 7;
            int ks = c0 >> 3;
            int reg = (c0 & 7) >> 2;
            int base = ks * 1089 + an * 68 + reg * 34 + nn * 4;
            uint32_t h, l;
            tf32_split(r.rb[i].x, h, l); buf[BHI + base + 0] = h; buf[BLO + base + 0] = l;
            tf32_split(r.rb[i].y, h, l); buf[BHI + base + 1] = h; buf[BLO + base + 1] = l;
            tf32_split(r.rb[i].z, h, l); buf[BHI + base + 2] = h; buf[BLO + base + 2] = l;
            tf32_split(r.rb[i].w, h, l); buf[BHI + base + 3] = h; buf[BLO + base + 3] = l;
        }
    }
}

__global__ __launch_bounds__(256, 2) void gemm_tf32_kernel(
    const float* __restrict__ A, const float* __restrict__ W,
    const float* __restrict__ bias, float* __restrict__ C,
    int N, int mode)
{
    extern __shared__ char dynsm[];
    uint32_t* smu = (uint32_t*)dynsm;
    const float* Ap = A ? A : g_attn;

    const int tid  = threadIdx.x;
    const int lane = tid & 31;
    const int wid  = tid >> 5;
    const int wr   = wid >> 2;
    const int wc   = wid & 3;
    const int m0 = blockIdx.y << 7;
    const int n0 = blockIdx.x << 7;

    float acc[4][4][4];
#pragma unroll
    for (int u = 0; u < 4; u++)
#pragma unroll
        for (int t = 0; t < 4; t++)
#pragma unroll
            for (int j = 0; j < 4; j++) acc[u][t][j] = 0.f;

    ChunkRegs cr;
    ldg_chunk(cr, Ap, W, m0, n0, 0, tid);
    sts_chunk(smu, cr, tid);
    __syncthreads();

    int p = 0;
    for (int c = 1; c <= GK / 16; c++) {
        if (c < GK / 16) ldg_chunk(cr, Ap, W, m0, n0, c, tid);

        const uint32_t* buf = smu + p * BUFU;
#pragma unroll
        for (int ks = 0; ks < 2; ks++) {
            uint32_t bh[4][2], bl[4][2];
#pragma unroll
            for (int t = 0; t < 4; t++) {
                int bidx = ks * 1089 + (wc * 4 + t) * 68 + lane;
                bh[t][0] = buf[BHI + bidx];   bh[t][1] = buf[BHI + bidx + 34];
                bl[t][0] = buf[BLO + bidx];   bl[t][1] = buf[BLO + bidx + 34];
            }
#pragma unroll
            for (int u = 0; u < 4; u++) {
                int a = ks * 1057 + (wr * 4 + u) * 132 + lane;
                uint32_t ah[4], al[4];
#pragma unroll
                for (int rg = 0; rg < 4; rg++) {
                    ah[rg] = buf[AHI + a + rg * 33];
                    al[rg] = buf[ALO + a + rg * 33];
                }
#pragma unroll
                for (int t = 0; t < 4; t++) {
                    mma_tf32(acc[u][t], ah[0], ah[1], ah[2], ah[3], bh[t][0], bh[t][1]);
                    mma_tf32(acc[u][t], ah[0], ah[1], ah[2], ah[3], bl[t][0], bl[t][1]);
                    mma_tf32(acc[u][t], al[0], al[1], al[2], al[3], bh[t][0], bh[t][1]);
                }
            }
        }

        if (c < GK / 16) {
            p ^= 1;
            sts_chunk(smu + p * BUFU, cr, tid);
            __syncthreads();
        }
    }

    const int grp = lane >> 2;
    const int tig = lane & 3;
#pragma unroll
    for (int u = 0; u < 4; u++) {
#pragma unroll
        for (int part = 0; part < 2; part++) {
            int m = m0 + wr * 64 + u * 16 + grp + part * 8;
            int bb = m >> 12;
            int s  = m & 4095;
#pragma unroll
            for (int t = 0; t < 4; t++) {
                int n = n0 + wc * 32 + t * 8 + tig * 2;
                float2 bv = *(const float2*)(bias + n);
                float2 r;
                r.x = acc[u][t][part * 2 + 0] + bv.x;
                r.y = acc[u][t][part * 2 + 1] + bv.y;
                if (mode == 0) {
                    int tt = n >> 10;
                    int h  = (n >> 6) & 15;
                    int d  = n & 63;
                    float* dst = ((tt == 0) ? g_q : (tt == 1) ? g_k : g_v)
                                 + (((size_t)bb * H_ + h) * S_ + s) * DH + d;
                    *(float2*)dst = r;
                } else {
                    *(float2*)&C[(size_t)m * N + n] = r;
                }
            }
        }
    }
}

// ---------------------------------------------------------------------------
// MMA flash attention. Block = 128 thr / 4 warps = one (b, h, 64-query tile).
// Warp w owns query rows w*16..w*16+15 (one m16). 16 key tiles of 64.
// S = QK^T: 3-term tf32 compensation (Q pre-scaled by 0.125, hi/lo split;
//           K hi/lo split).  PV: P and V single tf32 (~2e-4 rel each).
// SMEM (u32 idx):
//   QHI/QLO[w][ks][reg][lane]      stride 33  (A-frags, loaded once)
//   KHI/KLO[(ks*8+nt)*2+reg][lane] stride 33  (B-frags per key tile)
//   VF     [(ks*8+nt)*2+reg][lane] stride 33  (B-frags, k=key, n=d)
//   P      [row][key] stride 68 (A-frag reads map addr%32==lane: conflict-free)
// ---------------------------------------------------------------------------
#define AT_QHI 0
#define AT_QLO 4224
#define AT_KHI 8448
#define AT_KLO 12672
#define AT_VF  16896
#define AT_P   21120
#define ATT_SMEM2 ((21120 + 64 * 68) * 4)   // 101888 bytes

__global__ __launch_bounds__(128) void attn_mma_kernel()
{
    extern __shared__ char dynsm[];
    uint32_t* smw = (uint32_t*)dynsm;

    const int tid  = threadIdx.x;
    const int lane = tid & 31;
    const int w    = tid >> 5;
    const int g    = lane >> 2;      // row group 0..7
    const int q4   = lane & 3;
    const int qt = blockIdx.x;
    const int h  = blockIdx.y;
    const int b  = blockIdx.z;
    const int s0 = qt << 6;
    const int kbase = s0 & ~(SEG - 1);
    const size_t headoff = (((size_t)b * H_ + h) * S_) * DH;

    // ---- Load Q (64x64), scale by 0.125, split, store as A-frags ----
    {
        const float* qp = g_q + headoff + (size_t)s0 * DH;
#pragma unroll
        for (int i = 0; i < 8; i++) {
            int idx = tid + i * 128;
            int r  = idx >> 4;
            int d0 = (idx & 15) << 2;
            float4 v = *(const float4*)(qp + r * DH + d0);
            int wq  = r >> 4;
            int ks  = d0 >> 3;
            int reg = ((r & 15) >> 3) + (((d0 & 7) >> 2) << 1);
            int base = ((wq * 8 + ks) * 4 + reg) * 33 + (r & 7) * 4;
            uint32_t hh, ll;
            tf32_split(v.x * 0.125f, hh, ll); smw[AT_QHI+base+0]=hh; smw[AT_QLO+base+0]=ll;
            tf32_split(v.y * 0.125f, hh, ll); smw[AT_QHI+base+1]=hh; smw[AT_QLO+base+1]=ll;
            tf32_split(v.z * 0.125f, hh, ll); smw[AT_QHI+base+2]=hh; smw[AT_QLO+base+2]=ll;
            tf32_split(v.w * 0.125f, hh, ll); smw[AT_QHI+base+3]=hh; smw[AT_QLO+base+3]=ll;
        }
    }

    float o[8][4];
#pragma unroll
    for (int dt = 0; dt < 8; dt++)
#pragma unroll
        for (int j = 0; j < 4; j++) o[dt][j] = 0.f;
    float m0 = -1e30f, m1 = -1e30f, l0 = 0.f, l1 = 0.f;

    for (int kt = 0; kt < 16; kt++) {
        __syncthreads();   // prev iteration's KF/VF readers (incl. PV) done

        // ---- Load K (split) and V (single) tiles into frag-order smem ----
        {
            const float* kp = g_k + headoff + (size_t)(kbase + kt * 64) * DH;
            const float* vp = g_v + headoff + (size_t)(kbase + kt * 64) * DH;
#pragma unroll
            for (int i = 0; i < 8; i++) {
                int idx = tid + i * 128;
                int key = idx >> 4;
                int d0  = (idx & 15) << 2;
                float4 kv = *(const float4*)(kp + key * DH + d0);
                // K as B-frag: k=d, n=key
                int baseK = (((d0 >> 3) * 8 + (key >> 3)) * 2 + ((d0 & 7) >> 2)) * 33
                            + (key & 7) * 4;
                uint32_t hh, ll;
                tf32_split(kv.x, hh, ll); smw[AT_KHI+baseK+0]=hh; smw[AT_KLO+baseK+0]=ll;
                tf32_split(kv.y, hh, ll); smw[AT_KHI+baseK+1]=hh; smw[AT_KLO+baseK+1]=ll;
                tf32_split(kv.z, hh, ll); smw[AT_KHI+baseK+2]=hh; smw[AT_KLO+baseK+2]=ll;
                tf32_split(kv.w, hh, ll); smw[AT_KHI+baseK+3]=hh; smw[AT_KLO+baseK+3]=ll;
                float4 vv = *(const float4*)(vp + key * DH + d0);
                // V as B-frag: k=key, n=d
                int baseV = (((key >> 3) * 8 + (d0 >> 3)) * 2 + ((key & 7) >> 2)) * 33
                            + (d0 & 7) * 4 + (key & 3);
                smw[AT_VF+baseV+ 0] = tf32_one(vv.x);
                smw[AT_VF+baseV+ 4] = tf32_one(vv.y);
                smw[AT_VF+baseV+ 8] = tf32_one(vv.z);
                smw[AT_VF+baseV+12] = tf32_one(vv.w);
            }
        }
        __syncthreads();

        // ---- S = Q K^T (3-term compensated) ----
        float sacc[8][4];
#pragma unroll
        for (int nt = 0; nt < 8; nt++)
#pragma unroll
            for (int j = 0; j < 4; j++) sacc[nt][j] = 0.f;

#pragma unroll
        for (int ks = 0; ks < 8; ks++) {
            int ab = ((w * 8 + ks) * 4) * 33 + lane;
            uint32_t ah[4], al[4];
#pragma unroll
            for (int rg = 0; rg < 4; rg++) {
                ah[rg] = smw[AT_QHI + ab + rg * 33];
                al[rg] = smw[AT_QLO + ab + rg * 33];
            }
#pragma unroll
            for (int nt = 0; nt < 8; nt++) {
                int bb2 = ((ks * 8 + nt) * 2) * 33 + lane;
                uint32_t bh0 = smw[AT_KHI + bb2], bh1 = smw[AT_KHI + bb2 + 33];
                uint32_t bl0 = smw[AT_KLO + bb2], bl1 = smw[AT_KLO + bb2 + 33];
                mma_tf32(sacc[nt], ah[0], ah[1], ah[2], ah[3], bh0, bh1);
                mma_tf32(sacc[nt], ah[0], ah[1], ah[2], ah[3], bl0, bl1);
                mma_tf32(sacc[nt], al[0], al[1], al[2], al[3], bh0, bh1);
            }
        }

        // ---- Online softmax (rows g and g+8; reduce across quad lanes) ----
        float rmx0 = -1e30f, rmx1 = -1e30f;
#pragma unroll
        for (int nt = 0; nt < 8; nt++) {
            rmx0 = fmaxf(rmx0, fmaxf(sacc[nt][0], sacc[nt][1]));
            rmx1 = fmaxf(rmx1, fmaxf(sacc[nt][2], sacc[nt][3]));
        }
        rmx0 = fmaxf(rmx0, __shfl_xor_sync(0xffffffffu, rmx0, 1));
        rmx0 = fmaxf(rmx0, __shfl_xor_sync(0xffffffffu, rmx0, 2));
        rmx1 = fmaxf(rmx1, __shfl_xor_sync(0xffffffffu, rmx1, 1));
        rmx1 = fmaxf(rmx1, __shfl_xor_sync(0xffffffffu, rmx1, 2));
        float nm0 = fmaxf(m0, rmx0), nm1 = fmaxf(m1, rmx1);
        float c0 = __expf(m0 - nm0), c1 = __expf(m1 - nm1);
        float rs0 = 0.f, rs1 = 0.f;
        const int prow0 = AT_P + (w * 16 + g) * 68;
        const int prow1 = prow0 + 8 * 68;
#pragma unroll
        for (int nt = 0; nt < 8; nt++) {
            float p0 = __expf(sacc[nt][0] - nm0);
            float p1 = __expf(sacc[nt][1] - nm0);
            float p2 = __expf(sacc[nt][2] - nm1);
            float p3 = __expf(sacc[nt][3] - nm1);
            rs0 += p0 + p1;
            rs1 += p2 + p3;
            int col = nt * 8 + q4 * 2;
            smw[prow0 + col]     = tf32_one(p0);
            smw[prow0 + col + 1] = tf32_one(p1);
            smw[prow1 + col]     = tf32_one(p2);
            smw[prow1 + col + 1] = tf32_one(p3);
        }
        rs0 += __shfl_xor_sync(0xffffffffu, rs0, 1);
        rs0 += __shfl_xor_sync(0xffffffffu, rs0, 2);
        rs1 += __shfl_xor_sync(0xffffffffu, rs1, 1);
        rs1 += __shfl_xor_sync(0xffffffffu, rs1, 2);
        l0 = l0 * c0 + rs0;  m0 = nm0;
        l1 = l1 * c1 + rs1;  m1 = nm1;
#pragma unroll
        for (int dt = 0; dt < 8; dt++) {
            o[dt][0] *= c0; o[dt][1] *= c0;
            o[dt][2] *= c1; o[dt][3] *= c1;
        }
        __syncwarp();   // P is warp-local: order writes before A-frag reads

        // ---- O += P V ----
#pragma unroll
        for (int ks = 0; ks < 8; ks++) {
            int pa = AT_P + (w * 16 + g) * 68 + ks * 8 + q4;
            uint32_t a0 = smw[pa];
            uint32_t a1 = smw[pa + 8 * 68];
            uint32_t a2 = smw[pa + 4];
            uint32_t a3 = smw[pa + 8 * 68 + 4];
#pragma unroll
            for (int dt = 0; dt < 8; dt++) {
                int vb = AT_VF + ((ks * 8 + dt) * 2) * 33 + lane;
                mma_tf32(o[dt], a0, a1, a2, a3, smw[vb], smw[vb + 33]);
            }
        }
    }

    // ---- Normalize, write g_attn[b][s][h*64+d] ----
    float inv0 = 1.f / l0, inv1 = 1.f / l1;
    const int row0 = s0 + w * 16 + g;
#pragma unroll
    for (int dt = 0; dt < 8; dt++) {
        int col = dt * 8 + q4 * 2;
        float2 r0 = make_float2(o[dt][0] * inv0, o[dt][1] * inv0);
        float2 r1 = make_float2(o[dt][2] * inv1, o[dt][3] * inv1);
        *(float2*)&g_attn[((size_t)b * S_ + row0) * E_ + h * DH + col] = r0;
        *(float2*)&g_attn[((size_t)b * S_ + row0 + 8) * E_ + h * DH + col] = r1;
    }
}

// ---------------------------------------------------------------------------
// kernel_launch
// ---------------------------------------------------------------------------
extern "C" void kernel_launch(void* const* d_in, const int* in_sizes, int n_in,
                              void* d_out, int out_size)
{
    (void)in_sizes; (void)n_in; (void)out_size;
    const float* x     = (const float*)d_in[0];
    const float* w_qkv = (const float*)d_in[1];
    const float* b_qkv = (const float*)d_in[2];
    const float* w_out = (const float*)d_in[3];
    const float* b_out = (const float*)d_in[4];
    float* out = (float*)d_out;

    cudaFuncSetAttribute(gemm_tf32_kernel,
                         cudaFuncAttributeMaxDynamicSharedMemorySize, GEMM_SMEM);
    cudaFuncSetAttribute(attn_mma_kernel,
                         cudaFuncAttributeMaxDynamicSharedMemorySize, ATT_SMEM2);

    // 1) QKV projection: [8192,1024] x [3072,1024]^T -> scatter q/k/v
    {
        dim3 grid(3 * E_ / 128, (B_ * S_) / 128);   // (24, 64)
        gemm_tf32_kernel<<<grid, 256, GEMM_SMEM>>>(x, w_qkv, b_qkv, nullptr,
                                                   3 * E_, 0);
    }
    // 2) Segmented attention (mma.sync tf32)
    {
        dim3 grid(S_ / 64, H_, B_);                 // (64, 16, 2)
        attn_mma_kernel<<<grid, 128, ATT_SMEM2>>>();
    }
    // 3) Output projection: [8192,1024] x [1024,1024]^T -> d_out
    {
        dim3 grid(E_ / 128, (B_ * S_) / 128);       // (8, 64)
        gemm_tf32_kernel<<<grid, 256, GEMM_SMEM>>>(nullptr, w_out, b_out, out,
                                                   E_, 1);
    }
}

// round 13
// speedup vs baseline: 3.0525x; 1.7206x over previous
#include <cuda_runtime.h>
#include <cuda_bf16.h>
#include <cstdint>
#include <cstddef>

// Problem constants
#define B_  2
#define H_  16
#define S_  4096
#define DH  64
#define E_  1024
#define SEG 1024
#define GK  1024          // K of both GEMMs

// ---------------------------------------------------------------------------
// Scratch (device globals — no runtime allocation allowed)
// ---------------------------------------------------------------------------
__device__ float g_q[(size_t)B_ * H_ * S_ * DH];      // [b][h][s][d]
__device__ float g_k[(size_t)B_ * H_ * S_ * DH];
__device__ float g_v[(size_t)B_ * H_ * S_ * DH];
__device__ float g_attn[(size_t)B_ * S_ * E_];        // [b][s][h*64+d]

// ---------------------------------------------------------------------------
// Helpers (sm_80-era PTX only — NO tcgen05: harness targets plain sm_103)
// ---------------------------------------------------------------------------
__device__ __forceinline__ uint32_t tf32_one(float v) {
    uint32_t u;
    asm("cvt.rna.tf32.f32 %0, %1;" : "=r"(u) : "f"(v));
    return u;
}
// bf16 split: v = hi + lo, each representable in bf16 (8-bit mantissa)
__device__ __forceinline__ void bsplit(float v, float& hi, float& lo) {
    hi = __bfloat162float(__float2bfloat16(v));
    lo = v - hi;
}
// pack two floats as bf16x2; 'lo_k' = smaller k index -> lower 16 bits
__device__ __forceinline__ uint32_t bf2(float lo_k, float hi_k) {
    uint32_t u;
    asm("cvt.rn.bf16x2.f32 %0, %1, %2;" : "=r"(u) : "f"(hi_k), "f"(lo_k));
    return u;
}

__device__ __forceinline__ void mma_bf16(float* c,
    uint32_t a0, uint32_t a1, uint32_t a2, uint32_t a3,
    uint32_t b0, uint32_t b1)
{
    asm volatile(
        "mma.sync.aligned.m16n8k16.row.col.f32.bf16.bf16.f32 "
        "{%0,%1,%2,%3}, {%4,%5,%6,%7}, {%8,%9}, {%0,%1,%2,%3};"
        : "+f"(c[0]), "+f"(c[1]), "+f"(c[2]), "+f"(c[3])
        : "r"(a0), "r"(a1), "r"(a2), "r"(a3), "r"(b0), "r"(b1));
}
__device__ __forceinline__ void mma_tf32(float* c,
    uint32_t a0, uint32_t a1, uint32_t a2, uint32_t a3,
    uint32_t b0, uint32_t b1)
{
    asm volatile(
        "mma.sync.aligned.m16n8k8.row.col.f32.tf32.tf32.f32 "
        "{%0,%1,%2,%3}, {%4,%5,%6,%7}, {%8,%9}, {%0,%1,%2,%3};"
        : "+f"(c[0]), "+f"(c[1]), "+f"(c[2]), "+f"(c[3])
        : "r"(a0), "r"(a1), "r"(a2), "r"(a3), "r"(b0), "r"(b1));
}

// ---------------------------------------------------------------------------
// 3xBF16 GEMM: C[m][n] = sum_k A[m][k]*W[n][k] + bias[n]   ("NT", K=1024)
// BM=BN=128, BK=16 (one m16n8k16 step). 8 warps 2x4; warp tile 64x32.
// SMEM frag order, bf16x2-packed, stride 33 (conflict-free base+lane reads):
//   A[am][reg][lane]: am*132 + reg*33 + lane   (reg = (r%16>=8) + 2*(k>=8))
//   B[bn][reg][lane]: bn*66  + reg*33 + lane   (reg = (k>=8))
// 3 terms: hi*hi + hi*lo + lo*hi  (residual ~2^-16).
// Double-buffered + register prefetch. mode 0: scatter q/k/v; mode 1: store C.
// ---------------------------------------------------------------------------
#define AHI 0
#define ALO 1056
#define BHI 2112
#define BLO 3168
#define BUFU 4224                       // uint32 per buffer
#define GEMM_SMEM (2 * BUFU * 4)        // 33792 bytes

struct ChunkRegs { float4 ra[2], rb[2]; };

__device__ __forceinline__ void ldg_chunk(ChunkRegs& r, const float* Ap,
                                          const float* W, int m0, int n0,
                                          int c, int tid)
{
#pragma unroll
    for (int i = 0; i < 2; i++) {
        int f4 = tid + i * 256;
        int row = f4 >> 2;
        int c0 = (f4 & 3) << 2;
        r.ra[i] = *(const float4*)(Ap + (size_t)(m0 + row) * GK + c * 16 + c0);
        r.rb[i] = *(const float4*)(W  + (size_t)(n0 + row) * GK + c * 16 + c0);
    }
}

__device__ __forceinline__ void sts_chunk(uint32_t* buf, const ChunkRegs& r,
                                          int tid)
{
#pragma unroll
    for (int i = 0; i < 2; i++) {
        int f4 = tid + i * 256;
        int row = f4 >> 2;
        int c0 = (f4 & 3) << 2;           // k offset: 0,4,8,12
        const int kh = (c0 >> 3) & 1;     // k half
        const int qp = (c0 & 7) >> 1;     // k-pair within half: 0 or 2
        // ---- A ----
        {
            int am = row >> 4, rr = row & 15;
            int reg = (rr >> 3) + kh * 2;
            int base = am * 132 + reg * 33 + (rr & 7) * 4 + qp;
            float hx,lx,hy,ly,hz,lz,hw,lw;
            bsplit(r.ra[i].x,hx,lx); bsplit(r.ra[i].y,hy,ly);
            bsplit(r.ra[i].z,hz,lz); bsplit(r.ra[i].w,hw,lw);
            buf[AHI+base]   = bf2(hx,hy);  buf[AHI+base+1] = bf2(hz,hw);
            buf[ALO+base]   = bf2(lx,ly);  buf[ALO+base+1] = bf2(lz,lw);
        }
        // ---- B ----
        {
            int bn = row >> 3, nn = row & 7;
            int base = bn * 66 + kh * 33 + nn * 4 + qp;
            float hx,lx,hy,ly,hz,lz,hw,lw;
            bsplit(r.rb[i].x,hx,lx); bsplit(r.rb[i].y,hy,ly);
            bsplit(r.rb[i].z,hz,lz); bsplit(r.rb[i].w,hw,lw);
            buf[BHI+base]   = bf2(hx,hy);  buf[BHI+base+1] = bf2(hz,hw);
            buf[BLO+base]   = bf2(lx,ly);  buf[BLO+base+1] = bf2(lz,lw);
        }
    }
}

__global__ __launch_bounds__(256, 2) void gemm_bf16_kernel(
    const float* __restrict__ A, const float* __restrict__ W,
    const float* __restrict__ bias, float* __restrict__ C,
    int N, int mode)
{
    extern __shared__ char dynsm[];
    uint32_t* smu = (uint32_t*)dynsm;
    const float* Ap = A ? A : g_attn;

    const int tid  = threadIdx.x;
    const int lane = tid & 31;
    const int wid  = tid >> 5;
    const int wr   = wid >> 2;
    const int wc   = wid & 3;
    const int m0 = blockIdx.y << 7;
    const int n0 = blockIdx.x << 7;

    float acc[4][4][4];
#pragma unroll
    for (int u = 0; u < 4; u++)
#pragma unroll
        for (int t = 0; t < 4; t++)
#pragma unroll
            for (int j = 0; j < 4; j++) acc[u][t][j] = 0.f;

    ChunkRegs cr;
    ldg_chunk(cr, Ap, W, m0, n0, 0, tid);
    sts_chunk(smu, cr, tid);
    __syncthreads();

    int p = 0;
    for (int c = 1; c <= GK / 16; c++) {
        if (c < GK / 16) ldg_chunk(cr, Ap, W, m0, n0, c, tid);

        const uint32_t* buf = smu + p * BUFU;
        uint32_t bh[4][2], bl[4][2];
#pragma unroll
        for (int t = 0; t < 4; t++) {
            int bi = (wc * 4 + t) * 66 + lane;
            bh[t][0] = buf[BHI + bi];   bh[t][1] = buf[BHI + bi + 33];
            bl[t][0] = buf[BLO + bi];   bl[t][1] = buf[BLO + bi + 33];
        }
#pragma unroll
        for (int u = 0; u < 4; u++) {
            int ai = (wr * 4 + u) * 132 + lane;
            uint32_t ah[4], al[4];
#pragma unroll
            for (int rg = 0; rg < 4; rg++) {
                ah[rg] = buf[AHI + ai + rg * 33];
                al[rg] = buf[ALO + ai + rg * 33];
            }
#pragma unroll
            for (int t = 0; t < 4; t++) {
                mma_bf16(acc[u][t], ah[0], ah[1], ah[2], ah[3], bh[t][0], bh[t][1]);
                mma_bf16(acc[u][t], ah[0], ah[1], ah[2], ah[3], bl[t][0], bl[t][1]);
                mma_bf16(acc[u][t], al[0], al[1], al[2], al[3], bh[t][0], bh[t][1]);
            }
        }

        if (c < GK / 16) {
            p ^= 1;
            sts_chunk(smu + p * BUFU, cr, tid);
            __syncthreads();
        }
    }

    const int grp = lane >> 2;
    const int tig = lane & 3;
#pragma unroll
    for (int u = 0; u < 4; u++) {
#pragma unroll
        for (int part = 0; part < 2; part++) {
            int m = m0 + wr * 64 + u * 16 + grp + part * 8;
            int bb = m >> 12;
            int s  = m & 4095;
#pragma unroll
            for (int t = 0; t < 4; t++) {
                int n = n0 + wc * 32 + t * 8 + tig * 2;
                float2 bv = *(const float2*)(bias + n);
                float2 r;
                r.x = acc[u][t][part * 2 + 0] + bv.x;
                r.y = acc[u][t][part * 2 + 1] + bv.y;
                if (mode == 0) {
                    int tt = n >> 10;
                    int h  = (n >> 6) & 15;
                    int d  = n & 63;
                    float* dst = ((tt == 0) ? g_q : (tt == 1) ? g_k : g_v)
                                 + (((size_t)bb * H_ + h) * S_ + s) * DH + d;
                    *(float2*)dst = r;
                } else {
                    *(float2*)&C[(size_t)m * N + n] = r;
                }
            }
        }
    }
}

// ---------------------------------------------------------------------------
// MMA flash attention. Block = 128 thr / 4 warps = one (b, h, 64-query tile).
// S = QK^T: 3xBF16 m16n8k16 (Q pre-scaled 0.125, hi/lo split; K hi/lo split).
// PV: single tf32 m16n8k8 (validated 2.4e-4 budget).
// SMEM (u32): QHI/QLO 2112 ea; KHI/KLO 2112 ea; VF 4224 (tf32); P 64x68.
// ---------------------------------------------------------------------------
#define AT_QHI 0
#define AT_QLO 2112
#define AT_KHI 4224
#define AT_KLO 6336
#define AT_VF  8448
#define AT_P   12672
#define ATT_SMEM2 ((12672 + 64 * 68) * 4)   // 68096 bytes

__global__ __launch_bounds__(128, 3) void attn_mma_kernel()
{
    extern __shared__ char dynsm[];
    uint32_t* smw = (uint32_t*)dynsm;

    const int tid  = threadIdx.x;
    const int lane = tid & 31;
    const int w    = tid >> 5;
    const int g    = lane >> 2;
    const int q4   = lane & 3;
    const int qt = blockIdx.x;
    const int h  = blockIdx.y;
    const int b  = blockIdx.z;
    const int s0 = qt << 6;
    const int kbase = s0 & ~(SEG - 1);
    const size_t headoff = (((size_t)b * H_ + h) * S_) * DH;

    // ---- Load Q (64x64), scale 0.125, bf16-split, store as k16 A-frags ----
    {
        const float* qp = g_q + headoff + (size_t)s0 * DH;
#pragma unroll
        for (int i = 0; i < 8; i++) {
            int idx = tid + i * 128;
            int r  = idx >> 4;
            int d0 = (idx & 15) << 2;
            float4 v = *(const float4*)(qp + r * DH + d0);
            int wq  = r >> 4;
            int ks  = d0 >> 4;
            int reg = ((r & 15) >> 3) + (((d0 >> 3) & 1) << 1);
            int base = ((wq * 4 + ks) * 4 + reg) * 33 + (r & 7) * 4 + ((d0 & 7) >> 1);
            float hx,lx,hy,ly,hz,lz,hw,lw;
            bsplit(v.x * 0.125f, hx, lx); bsplit(v.y * 0.125f, hy, ly);
            bsplit(v.z * 0.125f, hz, lz); bsplit(v.w * 0.125f, hw, lw);
            smw[AT_QHI+base]   = bf2(hx,hy);  smw[AT_QHI+base+1] = bf2(hz,hw);
            smw[AT_QLO+base]   = bf2(lx,ly);  smw[AT_QLO+base+1] = bf2(lz,lw);
        }
    }

    float o[8][4];
#pragma unroll
    for (int dt = 0; dt < 8; dt++)
#pragma unroll
        for (int j = 0; j < 4; j++) o[dt][j] = 0.f;
    float m0 = -1e30f, m1 = -1e30f, l0 = 0.f, l1 = 0.f;

    for (int kt = 0; kt < 16; kt++) {
        __syncthreads();   // prev iteration's K/V readers done

        // ---- Load K (bf16 split, k16 B-frags) and V (tf32 k8 B-frags) ----
        {
            const float* kp = g_k + headoff + (size_t)(kbase + kt * 64) * DH;
            const float* vp = g_v + headoff + (size_t)(kbase + kt * 64) * DH;
#pragma unroll
            for (int i = 0; i < 8; i++) {
                int idx = tid + i * 128;
                int key = idx >> 4;
                int d0  = (idx & 15) << 2;
                float4 kv = *(const float4*)(kp + key * DH + d0);
                // K as bf16 B-frag: k=d (k16), n=key
                int baseK = (((d0 >> 4) * 8 + (key >> 3)) * 2 + ((d0 >> 3) & 1)) * 33
                            + (key & 7) * 4 + ((d0 & 7) >> 1);
                float hx,lx,hy,ly,hz,lz,hw,lw;
                bsplit(kv.x,hx,lx); bsplit(kv.y,hy,ly);
                bsplit(kv.z,hz,lz); bsplit(kv.w,hw,lw);
                smw[AT_KHI+baseK]   = bf2(hx,hy);  smw[AT_KHI+baseK+1] = bf2(hz,hw);
                smw[AT_KLO+baseK]   = bf2(lx,ly);  smw[AT_KLO+baseK+1] = bf2(lz,lw);
                float4 vv = *(const float4*)(vp + key * DH + d0);
                // V as tf32 B-frag: k=key (k8), n=d
                int baseV = (((key >> 3) * 8 + (d0 >> 3)) * 2 + ((key & 7) >> 2)) * 33
                            + (d0 & 7) * 4 + (key & 3);
                smw[AT_VF+baseV+ 0] = tf32_one(vv.x);
                smw[AT_VF+baseV+ 4] = tf32_one(vv.y);
                smw[AT_VF+baseV+ 8] = tf32_one(vv.z);
                smw[AT_VF+baseV+12] = tf32_one(vv.w);
            }
        }
        __syncthreads();

        // ---- S = Q K^T (3xBF16) ----
        float sacc[8][4];
#pragma unroll
        for (int nt = 0; nt < 8; nt++)
#pragma unroll
            for (int j = 0; j < 4; j++) sacc[nt][j] = 0.f;

#pragma unroll
        for (int ks = 0; ks < 4; ks++) {
            int ab = ((w * 4 + ks) * 4) * 33 + lane;
            uint32_t ah[4], al[4];
#pragma unroll
            for (int rg = 0; rg < 4; rg++) {
                ah[rg] = smw[AT_QHI + ab + rg * 33];
                al[rg] = smw[AT_QLO + ab + rg * 33];
            }
#pragma unroll
            for (int nt = 0; nt < 8; nt++) {
                int bb2 = ((ks * 8 + nt) * 2) * 33 + lane;
                uint32_t bh0 = smw[AT_KHI + bb2], bh1 = smw[AT_KHI + bb2 + 33];
                uint32_t bl0 = smw[AT_KLO + bb2], bl1 = smw[AT_KLO + bb2 + 33];
                mma_bf16(sacc[nt], ah[0], ah[1], ah[2], ah[3], bh0, bh1);
                mma_bf16(sacc[nt], ah[0], ah[1], ah[2], ah[3], bl0, bl1);
                mma_bf16(sacc[nt], al[0], al[1], al[2], al[3], bh0, bh1);
            }
        }

        // ---- Online softmax (rows g and g+8; reduce across quad lanes) ----
        float rmx0 = -1e30f, rmx1 = -1e30f;
#pragma unroll
        for (int nt = 0; nt < 8; nt++) {
            rmx0 = fmaxf(rmx0, fmaxf(sacc[nt][0], sacc[nt][1]));
            rmx1 = fmaxf(rmx1, fmaxf(sacc[nt][2], sacc[nt][3]));
        }
        rmx0 = fmaxf(rmx0, __shfl_xor_sync(0xffffffffu, rmx0, 1));
        rmx0 = fmaxf(rmx0, __shfl_xor_sync(0xffffffffu, rmx0, 2));
        rmx1 = fmaxf(rmx1, __shfl_xor_sync(0xffffffffu, rmx1, 1));
        rmx1 = fmaxf(rmx1, __shfl_xor_sync(0xffffffffu, rmx1, 2));
        float nm0 = fmaxf(m0, rmx0), nm1 = fmaxf(m1, rmx1);
        float c0 = __expf(m0 - nm0), c1 = __expf(m1 - nm1);
        float rs0 = 0.f, rs1 = 0.f;
        const int prow0 = AT_P + (w * 16 + g) * 68;
        const int prow1 = prow0 + 8 * 68;
#pragma unroll
        for (int nt = 0; nt < 8; nt++) {
            float p0 = __expf(sacc[nt][0] - nm0);
            float p1 = __expf(sacc[nt][1] - nm0);
            float p2 = __expf(sacc[nt][2] - nm1);
            float p3 = __expf(sacc[nt][3] - nm1);
            rs0 += p0 + p1;
            rs1 += p2 + p3;
            int col = nt * 8 + q4 * 2;
            smw[prow0 + col]     = tf32_one(p0);
            smw[prow0 + col + 1] = tf32_one(p1);
            smw[prow1 + col]     = tf32_one(p2);
            smw[prow1 + col + 1] = tf32_one(p3);
        }
        rs0 += __shfl_xor_sync(0xffffffffu, rs0, 1);
        rs0 += __shfl_xor_sync(0xffffffffu, rs0, 2);
        rs1 += __shfl_xor_sync(0xffffffffu, rs1, 1);
        rs1 += __shfl_xor_sync(0xffffffffu, rs1, 2);
        l0 = l0 * c0 + rs0;  m0 = nm0;
        l1 = l1 * c1 + rs1;  m1 = nm1;
#pragma unroll
        for (int dt = 0; dt < 8; dt++) {
            o[dt][0] *= c0; o[dt][1] *= c0;
            o[dt][2] *= c1; o[dt][3] *= c1;
        }
        __syncwarp();   // P is warp-local: order writes before A-frag reads

        // ---- O += P V  (tf32) ----
#pragma unroll
        for (int ks = 0; ks < 8; ks++) {
            int pa = AT_P + (w * 16 + g) * 68 + ks * 8 + q4;
            uint32_t a0 = smw[pa];
            uint32_t a1 = smw[pa + 8 * 68];
            uint32_t a2 = smw[pa + 4];
            uint32_t a3 = smw[pa + 8 * 68 + 4];
#pragma unroll
            for (int dt = 0; dt < 8; dt++) {
                int vb = AT_VF + ((ks * 8 + dt) * 2) * 33 + lane;
                mma_tf32(o[dt], a0, a1, a2, a3, smw[vb], smw[vb + 33]);
            }
        }
    }

    // ---- Normalize, write g_attn[b][s][h*64+d] ----
    float inv0 = 1.f / l0, inv1 = 1.f / l1;
    const int row0 = s0 + w * 16 + g;
#pragma unroll
    for (int dt = 0; dt < 8; dt++) {
        int col = dt * 8 + q4 * 2;
        float2 r0 = make_float2(o[dt][0] * inv0, o[dt][1] * inv0);
        float2 r1 = make_float2(o[dt][2] * inv1, o[dt][3] * inv1);
        *(float2*)&g_attn[((size_t)b * S_ + row0) * E_ + h * DH + col] = r0;
        *(float2*)&g_attn[((size_t)b * S_ + row0 + 8) * E_ + h * DH + col] = r1;
    }
}

// ---------------------------------------------------------------------------
// kernel_launch
// ---------------------------------------------------------------------------
extern "C" void kernel_launch(void* const* d_in, const int* in_sizes, int n_in,
                              void* d_out, int out_size)
{
    (void)in_sizes; (void)n_in; (void)out_size;
    const float* x     = (const float*)d_in[0];
    const float* w_qkv = (const float*)d_in[1];
    const float* b_qkv = (const float*)d_in[2];
    const float* w_out = (const float*)d_in[3];
    const float* b_out = (const float*)d_in[4];
    float* out = (float*)d_out;

    cudaFuncSetAttribute(gemm_bf16_kernel,
                         cudaFuncAttributeMaxDynamicSharedMemorySize, GEMM_SMEM);
    cudaFuncSetAttribute(attn_mma_kernel,
                         cudaFuncAttributeMaxDynamicSharedMemorySize, ATT_SMEM2);

    // 1) QKV projection: [8192,1024] x [3072,1024]^T -> scatter q/k/v
    {
        dim3 grid(3 * E_ / 128, (B_ * S_) / 128);   // (24, 64)
        gemm_bf16_kernel<<<grid, 256, GEMM_SMEM>>>(x, w_qkv, b_qkv, nullptr,
                                                   3 * E_, 0);
    }
    // 2) Segmented attention (bf16 S + tf32 PV)
    {
        dim3 grid(S_ / 64, H_, B_);                 // (64, 16, 2)
        attn_mma_kernel<<<grid, 128, ATT_SMEM2>>>();
    }
    // 3) Output projection: [8192,1024] x [1024,1024]^T -> d_out
    {
        dim3 grid(E_ / 128, (B_ * S_) / 128);       // (8, 64)
        gemm_bf16_kernel<<<grid, 256, GEMM_SMEM>>>(nullptr, w_out, b_out, out,
                                                   E_, 1);
    }
}